// round 2
// baseline (speedup 1.0000x reference)
#include <cuda_runtime.h>
#include <math.h>
#include <stdint.h>

#define T_DIM 4096
#define H_DIM 1024
#define E_DIM 8
#define K_TOP 2
#define I_DIM 2048
__device__ __constant__ float c_eps = 1e-5f;

// ---------------- scratch (static device globals; no allocations) ----------------
__device__ float g_normed[(size_t)T_DIM * H_DIM];                 // 16 MB
__device__ int   g_cnt[E_DIM];
__device__ int   g_tok[E_DIM * T_DIM];                            // token id per slot
__device__ int   g_slot[T_DIM * K_TOP];                           // slots per token
__device__ float g_wgt[T_DIM * K_TOP];                            // gate weights per token
__device__ float g_act[(size_t)E_DIM * T_DIM * I_DIM];            // 256 MB  (SwiGLU output)
__device__ float g_out2[(size_t)E_DIM * T_DIM * H_DIM];           // 128 MB  (expert outputs)

// ---------------- kernel 0: reset routing counters ----------------
__global__ void k_zero() {
    if (threadIdx.x < E_DIM) g_cnt[threadIdx.x] = 0;
}

// ---------------- kernel 1: RMSNorm + gate logits + top-2 softmax + routing ----------------
__global__ __launch_bounds__(256) void k_rms_gate(
    const float* __restrict__ x, const float* __restrict__ scale,
    const float* __restrict__ gk, const float* __restrict__ gb)
{
    const int t   = blockIdx.x;
    const int tid = threadIdx.x;

    __shared__ float sh[256];
    __shared__ float swar[8 * 8];   // [warp][expert]
    __shared__ float slog[8];

    // each thread owns 4 contiguous h values
    const float4 xv = *(const float4*)(x + (size_t)t * H_DIM + tid * 4);
    float ss = xv.x * xv.x + xv.y * xv.y + xv.z * xv.z + xv.w * xv.w;
    sh[tid] = ss;
    __syncthreads();
    for (int o = 128; o > 0; o >>= 1) {
        if (tid < o) sh[tid] += sh[tid + o];
        __syncthreads();
    }
    const float rinv = rsqrtf(sh[0] * (1.0f / H_DIM) + c_eps);

    const float4 sc = *(const float4*)(scale + tid * 4);
    float4 nv;
    nv.x = xv.x * rinv * sc.x;
    nv.y = xv.y * rinv * sc.y;
    nv.z = xv.z * rinv * sc.z;
    nv.w = xv.w * rinv * sc.w;
    *(float4*)(g_normed + (size_t)t * H_DIM + tid * 4) = nv;

    // gate logits: acc[e] += normed[h] * gk[h*E + e]
    float acc[E_DIM];
#pragma unroll
    for (int e = 0; e < E_DIM; e++) acc[e] = 0.f;
    float nvs[4] = {nv.x, nv.y, nv.z, nv.w};
#pragma unroll
    for (int c = 0; c < 4; c++) {
        const float* row = gk + (size_t)(tid * 4 + c) * E_DIM;
        const float4 r0 = *(const float4*)(row);
        const float4 r1 = *(const float4*)(row + 4);
        acc[0] += nvs[c] * r0.x; acc[1] += nvs[c] * r0.y;
        acc[2] += nvs[c] * r0.z; acc[3] += nvs[c] * r0.w;
        acc[4] += nvs[c] * r1.x; acc[5] += nvs[c] * r1.y;
        acc[6] += nvs[c] * r1.z; acc[7] += nvs[c] * r1.w;
    }
    const int lane = tid & 31, wid = tid >> 5;
#pragma unroll
    for (int e = 0; e < E_DIM; e++) {
        float v = acc[e];
#pragma unroll
        for (int o = 16; o > 0; o >>= 1) v += __shfl_down_sync(0xffffffffu, v, o);
        if (lane == 0) swar[wid * 8 + e] = v;
    }
    __syncthreads();
    if (tid < E_DIM) {
        float l = gb[tid];
#pragma unroll
        for (int w = 0; w < 8; w++) l += swar[w * 8 + tid];
        slog[tid] = l;
    }
    __syncthreads();

    if (tid == 0) {
        // top-2 (jax top_k tie-break: lowest index first -> strict >)
        int i0 = 0; float l0 = slog[0];
#pragma unroll
        for (int e = 1; e < E_DIM; e++) { if (slog[e] > l0) { l0 = slog[e]; i0 = e; } }
        int i1 = -1; float l1 = -3.4e38f;
#pragma unroll
        for (int e = 0; e < E_DIM; e++) {
            if (e != i0 && slog[e] > l1) { l1 = slog[e]; i1 = e; }
        }
        const float m  = fmaxf(l0, l1);
        const float e0 = expf(l0 - m), e1 = expf(l1 - m);
        const float inv = 1.0f / (e0 + e1);
        const float w0 = e0 * inv, w1 = e1 * inv;

        int p0 = atomicAdd(&g_cnt[i0], 1);
        int s0 = i0 * T_DIM + p0;
        g_tok[s0] = t; g_slot[2 * t + 0] = s0; g_wgt[2 * t + 0] = w0;
        int p1 = atomicAdd(&g_cnt[i1], 1);
        int s1 = i1 * T_DIM + p1;
        g_tok[s1] = t; g_slot[2 * t + 1] = s1; g_wgt[2 * t + 1] = w1;
    }
}

// ---------------- kernel 2: grouped GEMM1 (dual tile: gate+linear) + SwiGLU ----------------
// C_g[m,n] = sum_h A[m,h] * W1[e, n, h]          (n in [0,I))
// C_l[m,n] = sum_h A[m,h] * W1[e, I+n, h]
// act[slot,n] = swish(min(Cg+bg,7)) * (clip(Cl+bl,-7,7) + 1)
__global__ __launch_bounds__(256) void k_gemm1(
    const float* __restrict__ w1, const float* __restrict__ b1)
{
    const int e  = blockIdx.z;
    const int ne = g_cnt[e];
    const int m0 = blockIdx.y * 64;
    if (m0 >= ne) return;
    const int n0 = blockIdx.x * 64;

    __shared__ float As[16][68];
    __shared__ float Bg[16][68];
    __shared__ float Bl[16][68];
    __shared__ int   stok[64];

    const int tid = threadIdx.x;
    if (tid < 64) {
        const int m = m0 + tid;
        stok[tid] = (m < ne) ? g_tok[e * T_DIM + m] : -1;
    }
    __syncthreads();

    const int r  = tid >> 2;          // 0..63 (row/col of tile being loaded)
    const int kq = (tid & 3) * 4;     // k sub-offset
    const int tx = tid & 15, ty = tid >> 4;

    const float* w1g = w1 + ((size_t)e * 2 * I_DIM + (n0 + r)) * H_DIM;
    const float* w1l = w1g + (size_t)I_DIM * H_DIM;
    const int tokr = stok[r];
    const float* arow = (tokr >= 0) ? (g_normed + (size_t)tokr * H_DIM) : g_normed;
    const bool avalid = (tokr >= 0);

    float accg[4][4] = {}, accl[4][4] = {};

    for (int k0 = 0; k0 < H_DIM; k0 += 16) {
        float4 a4 = make_float4(0.f, 0.f, 0.f, 0.f);
        if (avalid) a4 = *(const float4*)(arow + k0 + kq);
        const float4 bg4 = *(const float4*)(w1g + k0 + kq);
        const float4 bl4 = *(const float4*)(w1l + k0 + kq);
        __syncthreads();
        As[kq + 0][r] = a4.x;  As[kq + 1][r] = a4.y;  As[kq + 2][r] = a4.z;  As[kq + 3][r] = a4.w;
        Bg[kq + 0][r] = bg4.x; Bg[kq + 1][r] = bg4.y; Bg[kq + 2][r] = bg4.z; Bg[kq + 3][r] = bg4.w;
        Bl[kq + 0][r] = bl4.x; Bl[kq + 1][r] = bl4.y; Bl[kq + 2][r] = bl4.z; Bl[kq + 3][r] = bl4.w;
        __syncthreads();
#pragma unroll
        for (int kk = 0; kk < 16; kk++) {
            const float4 av  = *(const float4*)&As[kk][ty * 4];
            const float4 bgv = *(const float4*)&Bg[kk][tx * 4];
            const float4 blv = *(const float4*)&Bl[kk][tx * 4];
            const float a[4]  = {av.x, av.y, av.z, av.w};
            const float bg[4] = {bgv.x, bgv.y, bgv.z, bgv.w};
            const float bl[4] = {blv.x, blv.y, blv.z, blv.w};
#pragma unroll
            for (int i = 0; i < 4; i++)
#pragma unroll
                for (int j = 0; j < 4; j++) {
                    accg[i][j] += a[i] * bg[j];
                    accl[i][j] += a[i] * bl[j];
                }
        }
    }

#pragma unroll
    for (int i = 0; i < 4; i++) {
        const int m = m0 + ty * 4 + i;
        if (m < ne) {
            float4 o;
#pragma unroll
            for (int j = 0; j < 4; j++) {
                const int n = n0 + tx * 4 + j;
                float gv = accg[i][j] + b1[e * 2 * I_DIM + n];
                float lv = accl[i][j] + b1[e * 2 * I_DIM + I_DIM + n];
                gv = fminf(gv, 7.f);
                lv = fminf(fmaxf(lv, -7.f), 7.f);
                const float sw = gv / (1.f + expf(-1.702f * gv));
                ((float*)&o)[j] = sw * (lv + 1.f);
            }
            *(float4*)(g_act + ((size_t)e * T_DIM + m) * I_DIM + n0 + tx * 4) = o;
        }
    }
}

// ---------------- kernel 3: grouped GEMM2 ----------------
// out2[slot,h] = sum_i act[slot,i] * W2[e, h, i] + b2[e,h]
__global__ __launch_bounds__(256) void k_gemm2(
    const float* __restrict__ w2, const float* __restrict__ b2)
{
    const int e  = blockIdx.z;
    const int ne = g_cnt[e];
    const int m0 = blockIdx.y * 64;
    if (m0 >= ne) return;
    const int h0 = blockIdx.x * 64;

    __shared__ float As[16][68];
    __shared__ float Bs[16][68];

    const int tid = threadIdx.x;
    const int r  = tid >> 2;
    const int kq = (tid & 3) * 4;
    const int tx = tid & 15, ty = tid >> 4;

    const bool avalid = (m0 + r) < ne;
    const float* arow = g_act + ((size_t)e * T_DIM + (avalid ? (m0 + r) : m0)) * I_DIM;
    const float* w2r  = w2 + ((size_t)e * H_DIM + (h0 + r)) * I_DIM;

    float acc[4][4] = {};

    for (int k0 = 0; k0 < I_DIM; k0 += 16) {
        float4 a4 = make_float4(0.f, 0.f, 0.f, 0.f);
        if (avalid) a4 = *(const float4*)(arow + k0 + kq);
        const float4 b4 = *(const float4*)(w2r + k0 + kq);
        __syncthreads();
        As[kq + 0][r] = a4.x; As[kq + 1][r] = a4.y; As[kq + 2][r] = a4.z; As[kq + 3][r] = a4.w;
        Bs[kq + 0][r] = b4.x; Bs[kq + 1][r] = b4.y; Bs[kq + 2][r] = b4.z; Bs[kq + 3][r] = b4.w;
        __syncthreads();
#pragma unroll
        for (int kk = 0; kk < 16; kk++) {
            const float4 av = *(const float4*)&As[kk][ty * 4];
            const float4 bv = *(const float4*)&Bs[kk][tx * 4];
            const float a[4] = {av.x, av.y, av.z, av.w};
            const float b[4] = {bv.x, bv.y, bv.z, bv.w};
#pragma unroll
            for (int i = 0; i < 4; i++)
#pragma unroll
                for (int j = 0; j < 4; j++)
                    acc[i][j] += a[i] * b[j];
        }
    }

#pragma unroll
    for (int i = 0; i < 4; i++) {
        const int m = m0 + ty * 4 + i;
        if (m < ne) {
            float4 o;
#pragma unroll
            for (int j = 0; j < 4; j++) {
                const int h = h0 + tx * 4 + j;
                ((float*)&o)[j] = acc[i][j] + b2[e * H_DIM + h];
            }
            *(float4*)(g_out2 + ((size_t)e * T_DIM + m) * H_DIM + h0 + tx * 4) = o;
        }
    }
}

// ---------------- kernel 4: gather-combine + residual ----------------
__global__ __launch_bounds__(256) void k_combine(
    const float* __restrict__ x, float* __restrict__ out)
{
    const size_t idx = (size_t)blockIdx.x * blockDim.x + threadIdx.x;  // over T*H/4
    if (idx >= (size_t)T_DIM * H_DIM / 4) return;
    const int t  = (int)(idx / (H_DIM / 4));
    const int hc = (int)(idx % (H_DIM / 4));

    const int   s0 = g_slot[2 * t + 0], s1 = g_slot[2 * t + 1];
    const float w0 = g_wgt[2 * t + 0],  w1 = g_wgt[2 * t + 1];

    const float4 xv = ((const float4*)x)[idx];
    const float4 o0 = *(const float4*)(g_out2 + (size_t)s0 * H_DIM + hc * 4);
    const float4 o1 = *(const float4*)(g_out2 + (size_t)s1 * H_DIM + hc * 4);
    float4 o;
    o.x = xv.x + w0 * o0.x + w1 * o1.x;
    o.y = xv.y + w0 * o0.y + w1 * o1.y;
    o.z = xv.z + w0 * o0.z + w1 * o1.z;
    o.w = xv.w + w0 * o0.w + w1 * o1.w;
    ((float4*)out)[idx] = o;
}

// ---------------- launch ----------------
extern "C" void kernel_launch(void* const* d_in, const int* in_sizes, int n_in,
                              void* d_out, int out_size)
{
    const float* x     = (const float*)d_in[0];
    const float* scale = (const float*)d_in[1];
    const float* gk    = (const float*)d_in[2];
    const float* gb    = (const float*)d_in[3];
    const float* w1    = (const float*)d_in[4];
    const float* b1    = (const float*)d_in[5];
    const float* w2    = (const float*)d_in[6];
    const float* b2    = (const float*)d_in[7];
    float* out = (float*)d_out;

    k_zero<<<1, 32>>>();
    k_rms_gate<<<T_DIM, 256>>>(x, scale, gk, gb);

    dim3 g1(I_DIM / 64, T_DIM / 64, E_DIM);   // 32 x 64 x 8
    k_gemm1<<<g1, 256>>>(w1, b1);

    dim3 g2(H_DIM / 64, T_DIM / 64, E_DIM);   // 16 x 64 x 8
    k_gemm2<<<g2, 256>>>(w2, b2);

    k_combine<<<(T_DIM * H_DIM / 4 + 255) / 256, 256>>>(x, out);
}

// round 4
// speedup vs baseline: 2.7910x; 2.7910x over previous
#include <cuda_runtime.h>
#include <math.h>
#include <stdint.h>

#define T_DIM 4096
#define H_DIM 1024
#define E_DIM 8
#define K_TOP 2
#define I_DIM 2048

// ---------------- scratch (static device globals; no allocations) ----------------
__device__ float g_normed[(size_t)T_DIM * H_DIM];                 // 16 MB
__device__ int   g_cnt[E_DIM];
__device__ int   g_tok[E_DIM * T_DIM];                            // token id per slot
__device__ int   g_slot[T_DIM * K_TOP];                           // slots per token
__device__ float g_wgt[T_DIM * K_TOP];                            // gate weights per token
__device__ float g_act[(size_t)E_DIM * T_DIM * I_DIM];            // 256 MB  (SwiGLU output)
__device__ float g_out2[(size_t)E_DIM * T_DIM * H_DIM];           // 128 MB  (expert outputs)

// ---------------- helpers ----------------
__device__ __forceinline__ uint32_t f2tf32(float x) {
    uint32_t r; asm("cvt.rna.tf32.f32 %0, %1;" : "=r"(r) : "f"(x)); return r;
}
__device__ __forceinline__ void mma_tf32(float* c, const uint32_t* a, const uint32_t* b) {
    asm("mma.sync.aligned.m16n8k8.row.col.f32.tf32.tf32.f32 "
        "{%0,%1,%2,%3},{%4,%5,%6,%7},{%8,%9},{%0,%1,%2,%3};"
        : "+f"(c[0]), "+f"(c[1]), "+f"(c[2]), "+f"(c[3])
        : "r"(a[0]), "r"(a[1]), "r"(a[2]), "r"(a[3]), "r"(b[0]), "r"(b[1]));
}
__device__ __forceinline__ void sts_tf32x4(float* dst, float4 v) {
    uint4 u = { f2tf32(v.x), f2tf32(v.y), f2tf32(v.z), f2tf32(v.w) };
    *(uint4*)dst = u;
}
__device__ __forceinline__ float swiglu(float gv, float lv) {
    gv = fminf(gv, 7.f);
    lv = fminf(fmaxf(lv, -7.f), 7.f);
    const float sw = gv / (1.f + expf(-1.702f * gv));
    return sw * (lv + 1.f);
}

// SMEM strides: K-tile = 32 floats per row, padded to 36 -> frag LDS bank-conflict-free
#define KT 32
#define ROWP 36

// ---------------- kernel 0: reset routing counters ----------------
__global__ void k_zero() {
    if (threadIdx.x < E_DIM) g_cnt[threadIdx.x] = 0;
}

// ---------------- kernel 1: RMSNorm + gate logits + top-2 softmax + routing ----------------
__global__ __launch_bounds__(256) void k_rms_gate(
    const float* __restrict__ x, const float* __restrict__ scale,
    const float* __restrict__ gk, const float* __restrict__ gb)
{
    const int t   = blockIdx.x;
    const int tid = threadIdx.x;

    __shared__ float sh[256];
    __shared__ float swar[8 * 8];
    __shared__ float slog[8];

    const float4 xv = *(const float4*)(x + (size_t)t * H_DIM + tid * 4);
    float ss = xv.x * xv.x + xv.y * xv.y + xv.z * xv.z + xv.w * xv.w;
    sh[tid] = ss;
    __syncthreads();
    for (int o = 128; o > 0; o >>= 1) {
        if (tid < o) sh[tid] += sh[tid + o];
        __syncthreads();
    }
    const float rinv = rsqrtf(sh[0] * (1.0f / H_DIM) + 1e-5f);

    const float4 sc = *(const float4*)(scale + tid * 4);
    float4 nv;
    nv.x = xv.x * rinv * sc.x;
    nv.y = xv.y * rinv * sc.y;
    nv.z = xv.z * rinv * sc.z;
    nv.w = xv.w * rinv * sc.w;
    *(float4*)(g_normed + (size_t)t * H_DIM + tid * 4) = nv;

    float acc[E_DIM];
#pragma unroll
    for (int e = 0; e < E_DIM; e++) acc[e] = 0.f;
    float nvs[4] = {nv.x, nv.y, nv.z, nv.w};
#pragma unroll
    for (int c = 0; c < 4; c++) {
        const float* row = gk + (size_t)(tid * 4 + c) * E_DIM;
        const float4 r0 = *(const float4*)(row);
        const float4 r1 = *(const float4*)(row + 4);
        acc[0] += nvs[c] * r0.x; acc[1] += nvs[c] * r0.y;
        acc[2] += nvs[c] * r0.z; acc[3] += nvs[c] * r0.w;
        acc[4] += nvs[c] * r1.x; acc[5] += nvs[c] * r1.y;
        acc[6] += nvs[c] * r1.z; acc[7] += nvs[c] * r1.w;
    }
    const int lane = tid & 31, wid = tid >> 5;
#pragma unroll
    for (int e = 0; e < E_DIM; e++) {
        float v = acc[e];
#pragma unroll
        for (int o = 16; o > 0; o >>= 1) v += __shfl_down_sync(0xffffffffu, v, o);
        if (lane == 0) swar[wid * 8 + e] = v;
    }
    __syncthreads();
    if (tid < E_DIM) {
        float l = gb[tid];
#pragma unroll
        for (int w = 0; w < 8; w++) l += swar[w * 8 + tid];
        slog[tid] = l;
    }
    __syncthreads();

    if (tid == 0) {
        int i0 = 0; float l0 = slog[0];
#pragma unroll
        for (int e = 1; e < E_DIM; e++) { if (slog[e] > l0) { l0 = slog[e]; i0 = e; } }
        int i1 = -1; float l1 = -3.4e38f;
#pragma unroll
        for (int e = 0; e < E_DIM; e++) {
            if (e != i0 && slog[e] > l1) { l1 = slog[e]; i1 = e; }
        }
        const float m  = fmaxf(l0, l1);
        const float e0 = expf(l0 - m), e1 = expf(l1 - m);
        const float inv = 1.0f / (e0 + e1);
        const float w0 = e0 * inv, w1 = e1 * inv;

        int p0 = atomicAdd(&g_cnt[i0], 1);
        int s0 = i0 * T_DIM + p0;
        g_tok[s0] = t; g_slot[2 * t + 0] = s0; g_wgt[2 * t + 0] = w0;
        int p1 = atomicAdd(&g_cnt[i1], 1);
        int s1 = i1 * T_DIM + p1;
        g_tok[s1] = t; g_slot[2 * t + 1] = s1; g_wgt[2 * t + 1] = w1;
    }
}

// ---------------- kernel 2: grouped GEMM1 (mma.sync tf32, dual gate+linear) + SwiGLU ----------------
// CTA tile: M=128 slots x (64 gate cols + 64 linear cols); 8 warps = 2(m) x 4(n)
// warp tile: 64 x (16 gate + 16 linear)
// SMEM per stage: A[128][36] + Bg[64][36] + Bl[64][36] floats (tf32 bits)
#define G1_STAGE ((128 + 64 + 64) * ROWP * 4)
#define G1_SMEM  (1024 + 2 * G1_STAGE)
__global__ __launch_bounds__(256) void k_gemm1(
    const float* __restrict__ w1, const float* __restrict__ b1)
{
    extern __shared__ char smem[];
    const int e  = blockIdx.z;
    const int ne = g_cnt[e];
    const int m0 = blockIdx.y * 128;
    if (m0 >= ne) return;
    const int n0 = blockIdx.x * 64;
    const int tid = threadIdx.x, lane = tid & 31, wid = tid >> 5;
    const int wm = wid >> 2, wn = wid & 3;

    int* stok = (int*)smem;
    if (tid < 128) stok[tid] = (m0 + tid < ne) ? g_tok[e * T_DIM + m0 + tid] : -1;
    __syncthreads();

    const float* w1g = w1 + ((size_t)e * 2 * I_DIM + n0) * H_DIM;
    const float* w1l = w1g + (size_t)I_DIM * H_DIM;

    float accg[4][2][4] = {}, accl[4][2][4] = {};

    // loader lanes: A: 4 chunks, Bg/Bl: 2 chunks each
    const int lrowA = tid >> 3;              // +128 per chunk? no: idx = tid + i*256
    const int lkq   = (tid & 7) * 4;
    (void)lrowA;

    float4 pa[4], pg[2], pl[2];
    // prologue: load tile 0
    {
        const int k0 = 0;
#pragma unroll
        for (int i = 0; i < 4; i++) {
            const int idx = tid + i * 256;
            const int r = idx >> 3;
            const int tok = stok[r];
            pa[i] = (tok >= 0) ? *(const float4*)(g_normed + (size_t)tok * H_DIM + k0 + lkq)
                               : make_float4(0.f, 0.f, 0.f, 0.f);
        }
#pragma unroll
        for (int i = 0; i < 2; i++) {
            const int idx = tid + i * 256;
            const int r = idx >> 3;
            pg[i] = *(const float4*)(w1g + (size_t)r * H_DIM + k0 + lkq);
            pl[i] = *(const float4*)(w1l + (size_t)r * H_DIM + k0 + lkq);
        }
        float* A  = (float*)(smem + 1024);
        float* Bg = A + 128 * ROWP;
        float* Bl = Bg + 64 * ROWP;
#pragma unroll
        for (int i = 0; i < 4; i++) sts_tf32x4(A + ((tid + i * 256) >> 3) * ROWP + lkq, pa[i]);
#pragma unroll
        for (int i = 0; i < 2; i++) {
            sts_tf32x4(Bg + ((tid + i * 256) >> 3) * ROWP + lkq, pg[i]);
            sts_tf32x4(Bl + ((tid + i * 256) >> 3) * ROWP + lkq, pl[i]);
        }
    }
    __syncthreads();

    const int NK = H_DIM / KT;   // 32
    for (int c = 0; c < NK; c++) {
        const float* A  = (const float*)(smem + 1024 + (c & 1) * G1_STAGE);
        const float* Bg = A + 128 * ROWP;
        const float* Bl = Bg + 64 * ROWP;
        const bool more = (c + 1 < NK);
        if (more) {
            const int k0 = (c + 1) * KT;
#pragma unroll
            for (int i = 0; i < 4; i++) {
                const int r = (tid + i * 256) >> 3;
                const int tok = stok[r];
                pa[i] = (tok >= 0) ? *(const float4*)(g_normed + (size_t)tok * H_DIM + k0 + lkq)
                                   : make_float4(0.f, 0.f, 0.f, 0.f);
            }
#pragma unroll
            for (int i = 0; i < 2; i++) {
                const int r = (tid + i * 256) >> 3;
                pg[i] = *(const float4*)(w1g + (size_t)r * H_DIM + k0 + lkq);
                pl[i] = *(const float4*)(w1l + (size_t)r * H_DIM + k0 + lkq);
            }
        }
#pragma unroll
        for (int ks = 0; ks < 4; ks++) {
            uint32_t af[4][4];
            const int kc = ks * 8 + (lane & 3);
            const int rb = wm * 64 + (lane >> 2);
#pragma unroll
            for (int mf = 0; mf < 4; mf++) {
                const int r = rb + mf * 16;
                af[mf][0] = __float_as_uint(A[r * ROWP + kc]);
                af[mf][1] = __float_as_uint(A[(r + 8) * ROWP + kc]);
                af[mf][2] = __float_as_uint(A[r * ROWP + kc + 4]);
                af[mf][3] = __float_as_uint(A[(r + 8) * ROWP + kc + 4]);
            }
            uint32_t bgf[2][2], blf[2][2];
#pragma unroll
            for (int nf = 0; nf < 2; nf++) {
                const int nn = wn * 16 + nf * 8 + (lane >> 2);
                bgf[nf][0] = __float_as_uint(Bg[nn * ROWP + kc]);
                bgf[nf][1] = __float_as_uint(Bg[nn * ROWP + kc + 4]);
                blf[nf][0] = __float_as_uint(Bl[nn * ROWP + kc]);
                blf[nf][1] = __float_as_uint(Bl[nn * ROWP + kc + 4]);
            }
#pragma unroll
            for (int mf = 0; mf < 4; mf++)
#pragma unroll
                for (int nf = 0; nf < 2; nf++) {
                    mma_tf32(accg[mf][nf], af[mf], bgf[nf]);
                    mma_tf32(accl[mf][nf], af[mf], blf[nf]);
                }
        }
        if (more) {
            float* An  = (float*)(smem + 1024 + ((c + 1) & 1) * G1_STAGE);
            float* Bgn = An + 128 * ROWP;
            float* Bln = Bgn + 64 * ROWP;
#pragma unroll
            for (int i = 0; i < 4; i++) sts_tf32x4(An + ((tid + i * 256) >> 3) * ROWP + lkq, pa[i]);
#pragma unroll
            for (int i = 0; i < 2; i++) {
                sts_tf32x4(Bgn + ((tid + i * 256) >> 3) * ROWP + lkq, pg[i]);
                sts_tf32x4(Bln + ((tid + i * 256) >> 3) * ROWP + lkq, pl[i]);
            }
        }
        __syncthreads();
    }

    // epilogue: bias + SwiGLU, write g_act
    const float* bgb = b1 + (size_t)e * 2 * I_DIM + n0;
    const float* blb = bgb + I_DIM;
#pragma unroll
    for (int mf = 0; mf < 4; mf++) {
        const int mbase = m0 + wm * 64 + mf * 16 + (lane >> 2);
#pragma unroll
        for (int h = 0; h < 2; h++) {
            const int m = mbase + h * 8;
            if (m < ne) {
                float* orow = g_act + ((size_t)e * T_DIM + m) * I_DIM + n0;
#pragma unroll
                for (int nf = 0; nf < 2; nf++) {
                    const int nloc = wn * 16 + nf * 8 + (lane & 3) * 2;
                    const float g0 = accg[mf][nf][2 * h + 0] + bgb[nloc];
                    const float g1 = accg[mf][nf][2 * h + 1] + bgb[nloc + 1];
                    const float l0 = accl[mf][nf][2 * h + 0] + blb[nloc];
                    const float l1 = accl[mf][nf][2 * h + 1] + blb[nloc + 1];
                    float2 o = { swiglu(g0, l0), swiglu(g1, l1) };
                    *(float2*)(orow + nloc) = o;
                }
            }
        }
    }
}

// ---------------- kernel 3: grouped GEMM2 (mma.sync tf32) + bias ----------------
// CTA tile: M=128 x N=128; warp tile 64x32; K = I = 2048
#define G2_STAGE ((128 + 128) * ROWP * 4)
#define G2_SMEM  (1024 + 2 * G2_STAGE)
__global__ __launch_bounds__(256) void k_gemm2(
    const float* __restrict__ w2, const float* __restrict__ b2)
{
    extern __shared__ char smem[];
    const int e  = blockIdx.z;
    const int ne = g_cnt[e];
    const int m0 = blockIdx.y * 128;
    if (m0 >= ne) return;
    const int n0 = blockIdx.x * 128;
    const int tid = threadIdx.x, lane = tid & 31, wid = tid >> 5;
    const int wm = wid >> 2, wn = wid & 3;

    const float* a_base = g_act + ((size_t)e * T_DIM + m0) * I_DIM;   // rows >= ne stay 0
    const float* b_base = w2 + ((size_t)e * H_DIM + n0) * I_DIM;
    const int lkq = (tid & 7) * 4;

    float acc[4][4][4] = {};
    float4 pa[4], pb[4];

    {
#pragma unroll
        for (int i = 0; i < 4; i++) {
            const int r = (tid + i * 256) >> 3;
            pa[i] = *(const float4*)(a_base + (size_t)r * I_DIM + lkq);
            pb[i] = *(const float4*)(b_base + (size_t)r * I_DIM + lkq);
        }
        float* A = (float*)(smem + 1024);
        float* B = A + 128 * ROWP;
#pragma unroll
        for (int i = 0; i < 4; i++) {
            sts_tf32x4(A + ((tid + i * 256) >> 3) * ROWP + lkq, pa[i]);
            sts_tf32x4(B + ((tid + i * 256) >> 3) * ROWP + lkq, pb[i]);
        }
    }
    __syncthreads();

    const int NK = I_DIM / KT;   // 64
    for (int c = 0; c < NK; c++) {
        const float* A = (const float*)(smem + 1024 + (c & 1) * G2_STAGE);
        const float* B = A + 128 * ROWP;
        const bool more = (c + 1 < NK);
        if (more) {
            const int k0 = (c + 1) * KT;
#pragma unroll
            for (int i = 0; i < 4; i++) {
                const int r = (tid + i * 256) >> 3;
                pa[i] = *(const float4*)(a_base + (size_t)r * I_DIM + k0 + lkq);
                pb[i] = *(const float4*)(b_base + (size_t)r * I_DIM + k0 + lkq);
            }
        }
#pragma unroll
        for (int ks = 0; ks < 4; ks++) {
            const int kc = ks * 8 + (lane & 3);
            uint32_t af[4][4];
            const int rb = wm * 64 + (lane >> 2);
#pragma unroll
            for (int mf = 0; mf < 4; mf++) {
                const int r = rb + mf * 16;
                af[mf][0] = __float_as_uint(A[r * ROWP + kc]);
                af[mf][1] = __float_as_uint(A[(r + 8) * ROWP + kc]);
                af[mf][2] = __float_as_uint(A[r * ROWP + kc + 4]);
                af[mf][3] = __float_as_uint(A[(r + 8) * ROWP + kc + 4]);
            }
            uint32_t bf[4][2];
#pragma unroll
            for (int nf = 0; nf < 4; nf++) {
                const int nn = wn * 32 + nf * 8 + (lane >> 2);
                bf[nf][0] = __float_as_uint(B[nn * ROWP + kc]);
                bf[nf][1] = __float_as_uint(B[nn * ROWP + kc + 4]);
            }
#pragma unroll
            for (int mf = 0; mf < 4; mf++)
#pragma unroll
                for (int nf = 0; nf < 4; nf++)
                    mma_tf32(acc[mf][nf], af[mf], bf[nf]);
        }
        if (more) {
            float* An = (float*)(smem + 1024 + ((c + 1) & 1) * G2_STAGE);
            float* Bn = An + 128 * ROWP;
#pragma unroll
            for (int i = 0; i < 4; i++) {
                sts_tf32x4(An + ((tid + i * 256) >> 3) * ROWP + lkq, pa[i]);
                sts_tf32x4(Bn + ((tid + i * 256) >> 3) * ROWP + lkq, pb[i]);
            }
        }
        __syncthreads();
    }

    const float* bb = b2 + (size_t)e * H_DIM + n0;
#pragma unroll
    for (int mf = 0; mf < 4; mf++) {
        const int mbase = m0 + wm * 64 + mf * 16 + (lane >> 2);
#pragma unroll
        for (int h = 0; h < 2; h++) {
            const int m = mbase + h * 8;
            if (m < ne) {
                float* orow = g_out2 + ((size_t)e * T_DIM + m) * H_DIM + n0;
#pragma unroll
                for (int nf = 0; nf < 4; nf++) {
                    const int nloc = wn * 32 + nf * 8 + (lane & 3) * 2;
                    float2 o = { acc[mf][nf][2 * h + 0] + bb[nloc],
                                 acc[mf][nf][2 * h + 1] + bb[nloc + 1] };
                    *(float2*)(orow + nloc) = o;
                }
            }
        }
    }
}

// ---------------- kernel 4: gather-combine + residual ----------------
__global__ __launch_bounds__(256) void k_combine(
    const float* __restrict__ x, float* __restrict__ out)
{
    const size_t idx = (size_t)blockIdx.x * blockDim.x + threadIdx.x;
    if (idx >= (size_t)T_DIM * H_DIM / 4) return;
    const int t  = (int)(idx / (H_DIM / 4));
    const int hc = (int)(idx % (H_DIM / 4));

    const int   s0 = g_slot[2 * t + 0], s1 = g_slot[2 * t + 1];
    const float w0 = g_wgt[2 * t + 0],  w1 = g_wgt[2 * t + 1];

    const float4 xv = ((const float4*)x)[idx];
    const float4 o0 = *(const float4*)(g_out2 + (size_t)s0 * H_DIM + hc * 4);
    const float4 o1 = *(const float4*)(g_out2 + (size_t)s1 * H_DIM + hc * 4);
    float4 o;
    o.x = xv.x + w0 * o0.x + w1 * o1.x;
    o.y = xv.y + w0 * o0.y + w1 * o1.y;
    o.z = xv.z + w0 * o0.z + w1 * o1.z;
    o.w = xv.w + w0 * o0.w + w1 * o1.w;
    ((float4*)out)[idx] = o;
}

// ---------------- launch ----------------
extern "C" void kernel_launch(void* const* d_in, const int* in_sizes, int n_in,
                              void* d_out, int out_size)
{
    const float* x     = (const float*)d_in[0];
    const float* scale = (const float*)d_in[1];
    const float* gk    = (const float*)d_in[2];
    const float* gb    = (const float*)d_in[3];
    const float* w1    = (const float*)d_in[4];
    const float* b1    = (const float*)d_in[5];
    const float* w2    = (const float*)d_in[6];
    const float* b2    = (const float*)d_in[7];
    float* out = (float*)d_out;

    cudaFuncSetAttribute(k_gemm1, cudaFuncAttributeMaxDynamicSharedMemorySize, G1_SMEM);
    cudaFuncSetAttribute(k_gemm2, cudaFuncAttributeMaxDynamicSharedMemorySize, G2_SMEM);

    k_zero<<<1, 32>>>();
    k_rms_gate<<<T_DIM, 256>>>(x, scale, gk, gb);

    dim3 g1(I_DIM / 64, T_DIM / 128, E_DIM);    // 32 x 32 x 8
    k_gemm1<<<g1, 256, G1_SMEM>>>(w1, b1);

    dim3 g2(H_DIM / 128, T_DIM / 128, E_DIM);   // 8 x 32 x 8
    k_gemm2<<<g2, 256, G2_SMEM>>>(w2, b2);

    k_combine<<<(T_DIM * H_DIM / 4 + 255) / 256, 256>>>(x, out);
}

// round 5
// speedup vs baseline: 6.6513x; 2.3831x over previous
#include <cuda_runtime.h>
#include <cuda_fp16.h>
#include <math.h>
#include <stdint.h>

#define T_DIM 4096
#define H_DIM 1024
#define E_DIM 8
#define I_DIM 2048
#define STAGES 3

// ---------------- scratch (static device globals; zero-initialized) ----------------
__device__ __half g_w1h[(size_t)E_DIM * 2 * I_DIM * H_DIM];   // 67 MB
__device__ __half g_w2h[(size_t)E_DIM * H_DIM * I_DIM];       // 33.5 MB
__device__ __half g_normed_h[(size_t)T_DIM * H_DIM];          // 8 MB
__device__ __half g_act_h[(size_t)E_DIM * T_DIM * I_DIM];     // 134 MB
__device__ float  g_out2[(size_t)E_DIM * T_DIM * H_DIM];      // 134 MB
__device__ int    g_cnt[E_DIM];
__device__ int    g_tok[E_DIM * T_DIM];
__device__ int    g_slot[T_DIM * 2];
__device__ float  g_wgt[T_DIM * 2];

// ---------------- PTX helpers ----------------
__device__ __forceinline__ uint32_t smem_u32(const void* p) {
    uint32_t a;
    asm("{ .reg .u64 t; cvta.to.shared.u64 t, %1; cvt.u32.u64 %0, t; }" : "=r"(a) : "l"(p));
    return a;
}
__device__ __forceinline__ void cp16(uint32_t dst, const void* src) {
    asm volatile("cp.async.cg.shared.global [%0], [%1], 16;" :: "r"(dst), "l"(src));
}
#define CP_COMMIT() asm volatile("cp.async.commit_group;" ::: "memory")
#define CP_WAIT1()  asm volatile("cp.async.wait_group 1;" ::: "memory")
__device__ __forceinline__ void ldsm4(uint32_t* r, uint32_t addr) {
    asm volatile("ldmatrix.sync.aligned.m8n8.x4.shared.b16 {%0,%1,%2,%3}, [%4];"
        : "=r"(r[0]), "=r"(r[1]), "=r"(r[2]), "=r"(r[3]) : "r"(addr));
}
__device__ __forceinline__ void mma_f16(float* c, const uint32_t* a, const uint32_t* b) {
    asm("mma.sync.aligned.m16n8k16.row.col.f32.f16.f16.f32 "
        "{%0,%1,%2,%3},{%4,%5,%6,%7},{%8,%9},{%0,%1,%2,%3};"
        : "+f"(c[0]), "+f"(c[1]), "+f"(c[2]), "+f"(c[3])
        : "r"(a[0]), "r"(a[1]), "r"(a[2]), "r"(a[3]), "r"(b[0]), "r"(b[1]));
}
__device__ __forceinline__ float swiglu(float gv, float lv) {
    gv = fminf(gv, 7.f);
    lv = fminf(fmaxf(lv, -7.f), 7.f);
    const float sw = gv / (1.f + expf(-1.702f * gv));
    return sw * (lv + 1.f);
}

// ---------------- kernel: fp32 -> fp16 conversion ----------------
__global__ __launch_bounds__(256) void k_cvt(const float4* __restrict__ src,
                                             uint2* __restrict__ dst, int n4)
{
    const int i = blockIdx.x * 256 + threadIdx.x;
    if (i < n4) {
        const float4 v = src[i];
        __half2 a = __floats2half2_rn(v.x, v.y);
        __half2 b = __floats2half2_rn(v.z, v.w);
        uint2 u;
        u.x = *(const uint32_t*)&a;
        u.y = *(const uint32_t*)&b;
        dst[i] = u;
    }
}

// ---------------- kernel 0: reset routing counters ----------------
__global__ void k_zero() {
    if (threadIdx.x < E_DIM) g_cnt[threadIdx.x] = 0;
}

// ---------------- kernel 1: RMSNorm + gate + top-2 + routing (writes fp16 normed) ----------------
__global__ __launch_bounds__(256) void k_rms_gate(
    const float* __restrict__ x, const float* __restrict__ scale,
    const float* __restrict__ gk, const float* __restrict__ gb)
{
    const int t   = blockIdx.x;
    const int tid = threadIdx.x;

    __shared__ float sh[256];
    __shared__ float swar[8 * 8];
    __shared__ float slog[8];

    const float4 xv = *(const float4*)(x + (size_t)t * H_DIM + tid * 4);
    float ss = xv.x * xv.x + xv.y * xv.y + xv.z * xv.z + xv.w * xv.w;
    sh[tid] = ss;
    __syncthreads();
    for (int o = 128; o > 0; o >>= 1) {
        if (tid < o) sh[tid] += sh[tid + o];
        __syncthreads();
    }
    const float rinv = rsqrtf(sh[0] * (1.0f / H_DIM) + 1e-5f);

    const float4 sc = *(const float4*)(scale + tid * 4);
    float4 nv;
    nv.x = xv.x * rinv * sc.x;
    nv.y = xv.y * rinv * sc.y;
    nv.z = xv.z * rinv * sc.z;
    nv.w = xv.w * rinv * sc.w;
    {
        __half2 a = __floats2half2_rn(nv.x, nv.y);
        __half2 b = __floats2half2_rn(nv.z, nv.w);
        uint2 u;
        u.x = *(const uint32_t*)&a;
        u.y = *(const uint32_t*)&b;
        *(uint2*)(g_normed_h + (size_t)t * H_DIM + tid * 4) = u;
    }

    float acc[E_DIM];
#pragma unroll
    for (int e = 0; e < E_DIM; e++) acc[e] = 0.f;
    float nvs[4] = {nv.x, nv.y, nv.z, nv.w};
#pragma unroll
    for (int c = 0; c < 4; c++) {
        const float* row = gk + (size_t)(tid * 4 + c) * E_DIM;
        const float4 r0 = *(const float4*)(row);
        const float4 r1 = *(const float4*)(row + 4);
        acc[0] += nvs[c] * r0.x; acc[1] += nvs[c] * r0.y;
        acc[2] += nvs[c] * r0.z; acc[3] += nvs[c] * r0.w;
        acc[4] += nvs[c] * r1.x; acc[5] += nvs[c] * r1.y;
        acc[6] += nvs[c] * r1.z; acc[7] += nvs[c] * r1.w;
    }
    const int lane = tid & 31, wid = tid >> 5;
#pragma unroll
    for (int e = 0; e < E_DIM; e++) {
        float v = acc[e];
#pragma unroll
        for (int o = 16; o > 0; o >>= 1) v += __shfl_down_sync(0xffffffffu, v, o);
        if (lane == 0) swar[wid * 8 + e] = v;
    }
    __syncthreads();
    if (tid < E_DIM) {
        float l = gb[tid];
#pragma unroll
        for (int w = 0; w < 8; w++) l += swar[w * 8 + tid];
        slog[tid] = l;
    }
    __syncthreads();

    if (tid == 0) {
        int i0 = 0; float l0 = slog[0];
#pragma unroll
        for (int e = 1; e < E_DIM; e++) { if (slog[e] > l0) { l0 = slog[e]; i0 = e; } }
        int i1 = -1; float l1 = -3.4e38f;
#pragma unroll
        for (int e = 0; e < E_DIM; e++) {
            if (e != i0 && slog[e] > l1) { l1 = slog[e]; i1 = e; }
        }
        const float m  = fmaxf(l0, l1);
        const float e0 = expf(l0 - m), e1 = expf(l1 - m);
        const float inv = 1.0f / (e0 + e1);

        int p0 = atomicAdd(&g_cnt[i0], 1);
        int s0 = i0 * T_DIM + p0;
        g_tok[s0] = t; g_slot[2 * t + 0] = s0; g_wgt[2 * t + 0] = e0 * inv;
        int p1 = atomicAdd(&g_cnt[i1], 1);
        int s1 = i1 * T_DIM + p1;
        g_tok[s1] = t; g_slot[2 * t + 1] = s1; g_wgt[2 * t + 1] = e1 * inv;
    }
}

// ======================= GEMM kernels (fp16 mma + ldmatrix + cp.async) =======================
// SMEM tile layout (per stage): A 128 rows x 64 halves (128B rows, XOR-swizzled 16B chunks),
// then B 128 rows x 64 halves. Stage = 32 KB.
// swizzle: chunk c (0..7) of row r stored at (c ^ (r & 7)).

#define STAGE_BYTES 32768
#define G1_SMEM (1024 + STAGES * STAGE_BYTES)
#define G2_SMEM (1024 + STAGES * STAGE_BYTES)

// ---------------- kernel 2: grouped GEMM1 + SwiGLU -> g_act_h ----------------
// CTA: M=128 slots x (64 gate + 64 linear cols). 8 warps = 2(m) x 4(n); warp: 64 x (16g+16l).
__global__ __launch_bounds__(256) void k_gemm1(const float* __restrict__ b1)
{
    extern __shared__ char smem[];
    const int e  = blockIdx.z;
    const int ne = g_cnt[e];
    const int m0 = blockIdx.y * 128;
    if (m0 >= ne) return;
    const int n0 = blockIdx.x * 64;
    const int tid = threadIdx.x, lane = tid & 31, wid = tid >> 5;
    const int wm = wid >> 2, wn = wid & 3;
    const uint32_t sb = smem_u32(smem);

    int* stok = (int*)smem;
    if (tid < 128) {
        const int m = m0 + tid;
        stok[tid] = g_tok[e * T_DIM + (m < ne ? m : ne - 1)];
    }
    __syncthreads();

    const __half* w1g = g_w1h + ((size_t)e * 2 * I_DIM + n0) * H_DIM;
    const __half* w1l = w1g + (size_t)I_DIM * H_DIM;

    // ---- loader addressing ----
    const int c8  = tid & 7;      // 16B chunk within row
    const int r32 = tid >> 3;     // 0..31
    const uint32_t swz = (uint32_t)((c8 ^ (r32 & 7)) << 4);
    const __half* asrc[4];
    const __half* bsrc[4];
    uint32_t adst[4], bdst[4];
#pragma unroll
    for (int i = 0; i < 4; i++) {
        const int row = r32 + i * 32;
        asrc[i] = g_normed_h + (size_t)stok[row] * H_DIM + c8 * 8;
        bsrc[i] = ((row < 64) ? (w1g + (size_t)row * H_DIM)
                              : (w1l + (size_t)(row - 64) * H_DIM)) + c8 * 8;
        adst[i] = sb + 1024u + (uint32_t)row * 128u + swz;
        bdst[i] = adst[i] + 16384u;
    }

#define G1_ISSUE(kt, s) do { \
    const uint32_t so = (uint32_t)(s) * STAGE_BYTES; \
    const int ko = (kt) * 64; \
    _Pragma("unroll") \
    for (int i = 0; i < 4; i++) { \
        cp16(adst[i] + so, asrc[i] + ko); \
        cp16(bdst[i] + so, bsrc[i] + ko); \
    } } while (0)

    const int NK = H_DIM / 64;   // 16
    G1_ISSUE(0, 0); CP_COMMIT();
    G1_ISSUE(1, 1); CP_COMMIT();

    float accg[4][2][4] = {}, accl[4][2][4] = {};

    const int lr  = lane & 7;
    const int rA  = ((lane >> 3) & 1) * 8 + lr;   // A row offset within frag
    const int cA  = (lane >> 4);                  // A chunk offset
    const int rB  = ((lane >> 4) & 1) * 8 + lr;   // B row offset
    const int cB  = ((lane >> 3) & 1);            // B chunk offset

    for (int c = 0; c < NK; c++) {
        CP_WAIT1();
        __syncthreads();
        if (c + 2 < NK) G1_ISSUE(c + 2, (c + 2) % STAGES);
        CP_COMMIT();

        const uint32_t Asm = sb + 1024u + (uint32_t)(c % STAGES) * STAGE_BYTES;
        const uint32_t Bsm = Asm + 16384u;
#pragma unroll
        for (int ks = 0; ks < 4; ks++) {
            uint32_t a[4][4];
            const uint32_t chA = (uint32_t)(((2 * ks + cA) ^ lr) << 4);
#pragma unroll
            for (int mf = 0; mf < 4; mf++) {
                const int row = wm * 64 + mf * 16 + rA;
                ldsm4(a[mf], Asm + (uint32_t)row * 128u + chA);
            }
            uint32_t bg[4], bl[4];
            const uint32_t chB = (uint32_t)(((2 * ks + cB) ^ lr) << 4);
            ldsm4(bg, Bsm + (uint32_t)(wn * 16 + rB) * 128u + chB);
            ldsm4(bl, Bsm + (uint32_t)(64 + wn * 16 + rB) * 128u + chB);
#pragma unroll
            for (int mf = 0; mf < 4; mf++) {
#pragma unroll
                for (int nf = 0; nf < 2; nf++) {
                    mma_f16(accg[mf][nf], a[mf], bg + 2 * nf);
                    mma_f16(accl[mf][nf], a[mf], bl + 2 * nf);
                }
            }
        }
    }

    // epilogue: bias + SwiGLU -> fp16 act
    const float* bgb = b1 + (size_t)e * 2 * I_DIM + n0;
    const float* blb = bgb + I_DIM;
#pragma unroll
    for (int mf = 0; mf < 4; mf++) {
        const int mb = m0 + wm * 64 + mf * 16 + (lane >> 2);
#pragma unroll
        for (int h = 0; h < 2; h++) {
            const int m = mb + h * 8;
            if (m < ne) {
                __half* orow = g_act_h + ((size_t)e * T_DIM + m) * I_DIM + n0;
#pragma unroll
                for (int nf = 0; nf < 2; nf++) {
                    const int nloc = wn * 16 + nf * 8 + 2 * (lane & 3);
                    const float g0 = accg[mf][nf][2 * h + 0] + bgb[nloc];
                    const float g1 = accg[mf][nf][2 * h + 1] + bgb[nloc + 1];
                    const float l0 = accl[mf][nf][2 * h + 0] + blb[nloc];
                    const float l1 = accl[mf][nf][2 * h + 1] + blb[nloc + 1];
                    __half2 o = __floats2half2_rn(swiglu(g0, l0), swiglu(g1, l1));
                    *(__half2*)(orow + nloc) = o;
                }
            }
        }
    }
#undef G1_ISSUE
}

// ---------------- kernel 3: grouped GEMM2 + bias -> g_out2 (fp32) ----------------
// CTA: M=128 x N=128; warp 64x32; K = I = 2048.
__global__ __launch_bounds__(256) void k_gemm2(const float* __restrict__ b2)
{
    extern __shared__ char smem[];
    const int e  = blockIdx.z;
    const int ne = g_cnt[e];
    const int m0 = blockIdx.y * 128;
    if (m0 >= ne) return;
    const int n0 = blockIdx.x * 128;
    const int tid = threadIdx.x, lane = tid & 31, wid = tid >> 5;
    const int wm = wid >> 2, wn = wid & 3;
    const uint32_t sb = smem_u32(smem);

    const __half* a_base = g_act_h + ((size_t)e * T_DIM + m0) * I_DIM;   // rows >= ne are zero
    const __half* b_base = g_w2h + ((size_t)e * H_DIM + n0) * I_DIM;

    const int c8  = tid & 7;
    const int r32 = tid >> 3;
    const uint32_t swz = (uint32_t)((c8 ^ (r32 & 7)) << 4);
    const __half* asrc[4];
    const __half* bsrc[4];
    uint32_t adst[4], bdst[4];
#pragma unroll
    for (int i = 0; i < 4; i++) {
        const int row = r32 + i * 32;
        asrc[i] = a_base + (size_t)row * I_DIM + c8 * 8;
        bsrc[i] = b_base + (size_t)row * I_DIM + c8 * 8;
        adst[i] = sb + 1024u + (uint32_t)row * 128u + swz;
        bdst[i] = adst[i] + 16384u;
    }

#define G2_ISSUE(kt, s) do { \
    const uint32_t so = (uint32_t)(s) * STAGE_BYTES; \
    const int ko = (kt) * 64; \
    _Pragma("unroll") \
    for (int i = 0; i < 4; i++) { \
        cp16(adst[i] + so, asrc[i] + ko); \
        cp16(bdst[i] + so, bsrc[i] + ko); \
    } } while (0)

    const int NK = I_DIM / 64;   // 32
    G2_ISSUE(0, 0); CP_COMMIT();
    G2_ISSUE(1, 1); CP_COMMIT();

    float acc[4][4][4] = {};

    const int lr  = lane & 7;
    const int rA  = ((lane >> 3) & 1) * 8 + lr;
    const int cA  = (lane >> 4);
    const int rB  = ((lane >> 4) & 1) * 8 + lr;
    const int cB  = ((lane >> 3) & 1);

    for (int c = 0; c < NK; c++) {
        CP_WAIT1();
        __syncthreads();
        if (c + 2 < NK) G2_ISSUE(c + 2, (c + 2) % STAGES);
        CP_COMMIT();

        const uint32_t Asm = sb + 1024u + (uint32_t)(c % STAGES) * STAGE_BYTES;
        const uint32_t Bsm = Asm + 16384u;
#pragma unroll
        for (int ks = 0; ks < 4; ks++) {
            uint32_t a[4][4];
            const uint32_t chA = (uint32_t)(((2 * ks + cA) ^ lr) << 4);
#pragma unroll
            for (int mf = 0; mf < 4; mf++) {
                const int row = wm * 64 + mf * 16 + rA;
                ldsm4(a[mf], Asm + (uint32_t)row * 128u + chA);
            }
            uint32_t b[2][4];
            const uint32_t chB = (uint32_t)(((2 * ks + cB) ^ lr) << 4);
            ldsm4(b[0], Bsm + (uint32_t)(wn * 32 + rB) * 128u + chB);
            ldsm4(b[1], Bsm + (uint32_t)(wn * 32 + 16 + rB) * 128u + chB);
#pragma unroll
            for (int mf = 0; mf < 4; mf++) {
#pragma unroll
                for (int nf = 0; nf < 4; nf++)
                    mma_f16(acc[mf][nf], a[mf], b[nf >> 1] + 2 * (nf & 1));
            }
        }
    }

    const float* bb = b2 + (size_t)e * H_DIM + n0;
#pragma unroll
    for (int mf = 0; mf < 4; mf++) {
        const int mb = m0 + wm * 64 + mf * 16 + (lane >> 2);
#pragma unroll
        for (int h = 0; h < 2; h++) {
            const int m = mb + h * 8;
            if (m < ne) {
                float* orow = g_out2 + ((size_t)e * T_DIM + m) * H_DIM + n0;
#pragma unroll
                for (int nf = 0; nf < 4; nf++) {
                    const int nloc = wn * 32 + nf * 8 + 2 * (lane & 3);
                    float2 o = { acc[mf][nf][2 * h + 0] + bb[nloc],
                                 acc[mf][nf][2 * h + 1] + bb[nloc + 1] };
                    *(float2*)(orow + nloc) = o;
                }
            }
        }
    }
#undef G2_ISSUE
}

// ---------------- kernel 4: gather-combine + residual ----------------
__global__ __launch_bounds__(256) void k_combine(
    const float* __restrict__ x, float* __restrict__ out)
{
    const size_t idx = (size_t)blockIdx.x * blockDim.x + threadIdx.x;
    if (idx >= (size_t)T_DIM * H_DIM / 4) return;
    const int t  = (int)(idx / (H_DIM / 4));
    const int hc = (int)(idx % (H_DIM / 4));

    const int   s0 = g_slot[2 * t + 0], s1 = g_slot[2 * t + 1];
    const float w0 = g_wgt[2 * t + 0],  w1 = g_wgt[2 * t + 1];

    const float4 xv = ((const float4*)x)[idx];
    const float4 o0 = *(const float4*)(g_out2 + (size_t)s0 * H_DIM + hc * 4);
    const float4 o1 = *(const float4*)(g_out2 + (size_t)s1 * H_DIM + hc * 4);
    float4 o;
    o.x = xv.x + w0 * o0.x + w1 * o1.x;
    o.y = xv.y + w0 * o0.y + w1 * o1.y;
    o.z = xv.z + w0 * o0.z + w1 * o1.z;
    o.w = xv.w + w0 * o0.w + w1 * o1.w;
    ((float4*)out)[idx] = o;
}

// ---------------- launch ----------------
extern "C" void kernel_launch(void* const* d_in, const int* in_sizes, int n_in,
                              void* d_out, int out_size)
{
    const float* x     = (const float*)d_in[0];
    const float* scale = (const float*)d_in[1];
    const float* gk    = (const float*)d_in[2];
    const float* gb    = (const float*)d_in[3];
    const float* w1    = (const float*)d_in[4];
    const float* b1    = (const float*)d_in[5];
    const float* w2    = (const float*)d_in[6];
    const float* b2    = (const float*)d_in[7];
    float* out = (float*)d_out;

    cudaFuncSetAttribute(k_gemm1, cudaFuncAttributeMaxDynamicSharedMemorySize, G1_SMEM);
    cudaFuncSetAttribute(k_gemm2, cudaFuncAttributeMaxDynamicSharedMemorySize, G2_SMEM);

    k_zero<<<1, 32>>>();

    // one-time-per-launch fp32 -> fp16 weight conversion
    {
        __half* w1h_p; cudaGetSymbolAddress((void**)&w1h_p, g_w1h);
        __half* w2h_p; cudaGetSymbolAddress((void**)&w2h_p, g_w2h);
        const int n4_1 = E_DIM * 2 * I_DIM * H_DIM / 4;   // 16.7M
        const int n4_2 = E_DIM * H_DIM * I_DIM / 4;       // 4.2M
        k_cvt<<<n4_1 / 256, 256>>>((const float4*)w1, (uint2*)w1h_p, n4_1);
        k_cvt<<<n4_2 / 256, 256>>>((const float4*)w2, (uint2*)w2h_p, n4_2);
    }

    k_rms_gate<<<T_DIM, 256>>>(x, scale, gk, gb);

    dim3 g1(I_DIM / 64, T_DIM / 128, E_DIM);    // 32 x 32 x 8
    k_gemm1<<<g1, 256, G1_SMEM>>>(b1);

    dim3 g2(H_DIM / 128, T_DIM / 128, E_DIM);   // 8 x 32 x 8
    k_gemm2<<<g2, 256, G2_SMEM>>>(b2);

    k_combine<<<(T_DIM * H_DIM / 4 + 255) / 256, 256>>>(x, out);
}